// round 1
// baseline (speedup 1.0000x reference)
#include <cuda_runtime.h>
#include <math.h>
#include <float.h>

// Problem constants (fixed by the dataset)
#define BB 1024
#define LL 81      // sequence length = WS*WS
#define HH 8
#define DD 64
#define UU 10      // top-k rows: min(2*ceil(log(81)), 81) = 10
#define NSAMP 41   // (81+1)/2 even-index key samples
#define WS 9
#define KSTR 68    // padded K row stride (floats) for bank-conflict relief

#define NTHREADS 256

// Shared memory layout (floats):
//   Qs   : LL*DD      = 5184   (also reused as context buffer in phase E)
//   Ks   : LL*KSTR    = 5508
//   Vs   : LL*DD      = 5184
//   Ms   : LL         = 81
//   bias : 289
//   attn : UU*LL      = 810
//   upd  : UU*DD      = 640
//   topi : UU ints
//   rank : LL ints
#define SM_FLOATS (LL*DD + LL*KSTR + LL*DD + LL + 289 + UU*LL + UU*DD)
#define SM_BYTES  (SM_FLOATS*4 + (UU + LL)*4 + 64)

__global__ __launch_bounds__(NTHREADS, 1)
void prob_attn_kernel(const float* __restrict__ q_in,
                      const float* __restrict__ k_in,
                      const float* __restrict__ v_in,
                      const float* __restrict__ bias_in,
                      float* __restrict__ out_ctx,
                      float* __restrict__ out_attn)
{
    extern __shared__ float sm[];
    float* Qs    = sm;
    float* Ks    = Qs + LL*DD;
    float* Vs    = Ks + LL*KSTR;
    float* Ms    = Vs + LL*DD;
    float* biass = Ms + LL;
    float* attns = biass + 289;
    float* upds  = attns + UU*LL;
    int*   topi  = (int*)(upds + UU*DD);
    int*   rank_of = topi + UU;

    const int tid  = threadIdx.x;
    const int warp = tid >> 5;
    const int lane = tid & 31;

    const int blk = blockIdx.x;
    const int b = blk >> 3;      // / HH
    const int h = blk & 7;       // % HH

    const size_t base = ((size_t)b * LL * HH + h) * DD;   // row l at base + l*HH*DD
    const float* qb = q_in + base;
    const float* kb = k_in + base;
    const float* vb = v_in + base;

    // ---- Phase A: load tiles (coalesced float4), bias table, init rank map ----
    for (int idx = tid; idx < LL * 16; idx += NTHREADS) {
        int row = idx >> 4;
        int vec = idx & 15;
        size_t goff = (size_t)row * (HH * DD) + vec * 4;
        float4 qv = *(const float4*)(qb + goff);
        float4 kv = *(const float4*)(kb + goff);
        float4 vv = *(const float4*)(vb + goff);
        *(float4*)(Qs + row*DD + vec*4) = qv;
        *(float4*)(Ks + row*KSTR + vec*4) = kv;   // KSTR multiple of 4 -> 16B aligned
        *(float4*)(Vs + row*DD + vec*4) = vv;
    }
    for (int i = tid; i < 289; i += NTHREADS) biass[i] = bias_in[i];
    if (tid < LL) rank_of[tid] = -1;
    __syncthreads();

    // ---- Phase B: sparsity measure M[q] = max_s(QK_s) - sum_s(QK_s)/81 ----
    // warp per q; lane over even-sampled keys
    for (int q = warp; q < LL; q += 8) {
        const float* qr = Qs + q * DD;
        float mx = -FLT_MAX;
        float sum = 0.0f;
        #pragma unroll
        for (int t = 0; t < 2; t++) {
            int s = lane + t * 32;
            if (s < NSAMP) {
                const float* kr = Ks + (2 * s) * KSTR;
                float acc = 0.0f;
                #pragma unroll
                for (int d = 0; d < DD; d += 4) {
                    float4 a = *(const float4*)(qr + d);
                    float4 kk4 = *(const float4*)(kr + d);
                    acc += a.x * kk4.x + a.y * kk4.y + a.z * kk4.z + a.w * kk4.w;
                }
                mx = fmaxf(mx, acc);
                sum += acc;
            }
        }
        #pragma unroll
        for (int o = 16; o > 0; o >>= 1) {
            mx  = fmaxf(mx, __shfl_xor_sync(0xffffffffu, mx, o));
            sum += __shfl_xor_sync(0xffffffffu, sum, o);
        }
        if (lane == 0) Ms[q] = mx - sum * (1.0f / 81.0f);
    }
    __syncthreads();

    // ---- Phase C: top-10 selection (serial; strict '>' => lower index on ties,
    //      matching jax.lax.top_k stability) ----
    if (tid == 0) {
        #pragma unroll
        for (int r = 0; r < UU; r++) {
            float best = -FLT_MAX; int bi = 0;
            for (int q = 0; q < LL; q++) {
                float v = Ms[q];
                if (v > best) { best = v; bi = q; }
            }
            topi[r] = bi;
            rank_of[bi] = r;
            Ms[bi] = -FLT_MAX;
        }
    }
    __syncthreads();

    // ---- Phase D: full scores for selected rows, +bias(rank,k), softmax, PV ----
    const float scale = 0.125f; // 1/sqrt(64)
    for (int r = warp; r < UU; r += 8) {
        const int qi = topi[r];
        const float* qr = Qs + qi * DD;
        const int ri = r / WS, rj = r % WS;   // NOTE: bias row indexed by RANK (reference quirk)

        float sc[3];
        float mx = -FLT_MAX;
        #pragma unroll
        for (int t = 0; t < 3; t++) {
            int k = lane + t * 32;
            float v = -FLT_MAX;
            if (k < LL) {
                const float* kr = Ks + k * KSTR;
                float acc = 0.0f;
                #pragma unroll
                for (int d = 0; d < DD; d += 4) {
                    float4 a = *(const float4*)(qr + d);
                    float4 kk4 = *(const float4*)(kr + d);
                    acc += a.x * kk4.x + a.y * kk4.y + a.z * kk4.z + a.w * kk4.w;
                }
                int ki = k / WS, kj = k % WS;
                int bidx = (ri - ki + (WS - 1)) * (2 * WS - 1) + (rj - kj + (WS - 1));
                v = (acc + biass[bidx]) * scale;
            }
            sc[t] = v;
            mx = fmaxf(mx, v);
        }
        #pragma unroll
        for (int o = 16; o > 0; o >>= 1)
            mx = fmaxf(mx, __shfl_xor_sync(0xffffffffu, mx, o));

        float sum = 0.0f;
        #pragma unroll
        for (int t = 0; t < 3; t++) {
            int k = lane + t * 32;
            if (k < LL) { sc[t] = __expf(sc[t] - mx); sum += sc[t]; }
        }
        #pragma unroll
        for (int o = 16; o > 0; o >>= 1)
            sum += __shfl_xor_sync(0xffffffffu, sum, o);
        const float inv = 1.0f / sum;

        #pragma unroll
        for (int t = 0; t < 3; t++) {
            int k = lane + t * 32;
            if (k < LL) attns[r * LL + k] = sc[t] * inv;
        }
        __syncwarp();

        // upd[r] = attn_row @ V  (lane over d; V reads conflict-free)
        #pragma unroll
        for (int dd = 0; dd < 2; dd++) {
            int d = lane + dd * 32;
            float acc = 0.0f;
            for (int k = 0; k < LL; k++)
                acc += attns[r * LL + k] * Vs[k * DD + d];
            upds[r * DD + d] = acc;
        }
    }
    __syncthreads();

    // ---- attn output (second tuple element), contiguous per (b,h) ----
    if (out_attn) {
        float* ao = out_attn + (((size_t)b * HH + h) * UU) * LL;
        for (int i = tid; i < UU * LL; i += NTHREADS) ao[i] = attns[i];
    }

    // ---- Phase E: cumsum(V) with top rows replaced by upd; reuse Qs as ctx ----
    if (tid < DD) {
        const int d = tid;
        float acc = 0.0f;
        for (int l = 0; l < LL; l++) {
            acc += Vs[l * DD + d];
            int r = rank_of[l];
            Qs[l * DD + d] = (r >= 0) ? upds[r * DD + d] : acc;
        }
    }
    __syncthreads();

    // ---- write context (coalesced float4) ----
    float* ob = out_ctx + base;
    for (int idx = tid; idx < LL * 16; idx += NTHREADS) {
        int row = idx >> 4;
        int vec = idx & 15;
        *(float4*)(ob + (size_t)row * (HH * DD) + vec * 4) =
            *(const float4*)(Qs + row * DD + vec * 4);
    }
}

extern "C" void kernel_launch(void* const* d_in, const int* in_sizes, int n_in,
                              void* d_out, int out_size)
{
    const float* q    = (const float*)d_in[0];
    const float* k    = (const float*)d_in[1];
    const float* v    = (const float*)d_in[2];
    const float* bias = (const float*)d_in[3];
    float* out = (float*)d_out;

    const long long ctx_elems  = (long long)BB * LL * HH * DD;   // 42,467,328
    const long long attn_elems = (long long)BB * HH * UU * LL;   //  6,635,520
    float* attn_out = ((long long)out_size >= ctx_elems + attn_elems)
                        ? out + ctx_elems : nullptr;

    cudaFuncSetAttribute(prob_attn_kernel,
                         cudaFuncAttributeMaxDynamicSharedMemorySize, SM_BYTES);
    prob_attn_kernel<<<BB * HH, NTHREADS, SM_BYTES>>>(q, k, v, bias, out, attn_out);
}

// round 2
// speedup vs baseline: 2.3233x; 2.3233x over previous
#include <cuda_runtime.h>
#include <math.h>
#include <float.h>

// Problem constants (fixed by the dataset)
#define BB 1024
#define LL 81      // sequence length = WS*WS
#define HH 8
#define DD 64
#define UU 10      // top-k rows
#define NSAMP 41   // (81+1)/2 even-index key samples
#define WS 9
#define QSTR 68    // padded Q row stride (floats)
#define KSTR 68    // padded K row stride (floats)

#define NTHREADS 256

// Shared memory layout (floats):
//   Qs   : 81*68 = 5508   (reused as context buffer in phase E)
//   Ks   : 81*68 = 5508
//   Vs   : 81*64 = 5184
//   bias : 289
//   Ms   : 84
//   pmx  : 11*84 = 924   (phase-B partial max per s-tile)
//   psm  : 11*84 = 924   (phase-B partial sum per s-tile)
//   upd  : 10*64 = 640
//   topi : 16 ints, rank_of : 81 ints
#define SM_FLOATS (81*QSTR + 81*KSTR + 81*DD + 289 + 84 + 924 + 924 + 640)
#define SM_BYTES  (SM_FLOATS*4 + (16 + 81)*4)

__global__ __launch_bounds__(NTHREADS, 3)
void prob_attn_kernel(const float* __restrict__ q_in,
                      const float* __restrict__ k_in,
                      const float* __restrict__ v_in,
                      const float* __restrict__ bias_in,
                      float* __restrict__ out_ctx,
                      float* __restrict__ out_attn)
{
    extern __shared__ float sm[];
    float* Qs    = sm;
    float* Ks    = Qs + 81*QSTR;
    float* Vs    = Ks + 81*KSTR;
    float* biass = Vs + 81*DD;
    float* Ms    = biass + 289;
    float* pmx   = Ms + 84;
    float* psm   = pmx + 924;
    float* upds  = psm + 924;
    int*   topi  = (int*)(upds + 640);
    int*   rank_of = topi + 16;

    const int tid  = threadIdx.x;
    const int warp = tid >> 5;
    const int lane = tid & 31;

    const int blk = blockIdx.x;
    const int b = blk >> 3;
    const int h = blk & 7;

    const size_t base = ((size_t)b * LL * HH + h) * DD;   // row l at base + l*HH*DD
    const float* qb = q_in + base;
    const float* kb = k_in + base;
    const float* vb = v_in + base;

    // ---- Phase A: load tiles (coalesced float4), bias, init rank map ----
    for (int idx = tid; idx < LL * 16; idx += NTHREADS) {
        int row = idx >> 4;
        int vec = idx & 15;
        size_t goff = (size_t)row * (HH * DD) + vec * 4;
        float4 qv = *(const float4*)(qb + goff);
        float4 kv = *(const float4*)(kb + goff);
        float4 vv = *(const float4*)(vb + goff);
        *(float4*)(Qs + row*QSTR + vec*4) = qv;
        *(float4*)(Ks + row*KSTR + vec*4) = kv;
        *(float4*)(Vs + row*DD   + vec*4) = vv;
    }
    for (int i = tid; i < 289; i += NTHREADS) biass[i] = bias_in[i];
    if (tid < LL) rank_of[tid] = -1;
    __syncthreads();

    // ---- Phase B: sampled scores, register-tiled 4q x 4s per thread ----
    // thread t < 231: st = t/21 (0..10), qt = t%21 (0..20)
    if (tid < 231) {
        const int st = tid / 21;
        const int qt = tid - st * 21;
        const int q0 = qt * 4;
        const int s0 = st * 4;
        const float* Qb = Qs + q0 * QSTR;
        const float* Kb = Ks + (2 * s0) * KSTR;

        float acc[4][4];
        #pragma unroll
        for (int i = 0; i < 4; i++)
            #pragma unroll
            for (int j = 0; j < 4; j++) acc[i][j] = 0.0f;

        #pragma unroll 2
        for (int d = 0; d < DD; d += 4) {
            float4 qv[4], kv[4];
            #pragma unroll
            for (int i = 0; i < 4; i++)
                qv[i] = *(const float4*)(Qb + i * QSTR + d);
            #pragma unroll
            for (int j = 0; j < 4; j++)
                kv[j] = *(const float4*)(Kb + j * 2 * KSTR + d);
            #pragma unroll
            for (int i = 0; i < 4; i++)
                #pragma unroll
                for (int j = 0; j < 4; j++)
                    acc[i][j] += qv[i].x*kv[j].x + qv[i].y*kv[j].y
                               + qv[i].z*kv[j].z + qv[i].w*kv[j].w;
        }

        #pragma unroll
        for (int i = 0; i < 4; i++) {
            int q = q0 + i;
            if (q < LL) {
                float mx = -FLT_MAX, smv = 0.0f;
                #pragma unroll
                for (int j = 0; j < 4; j++) {
                    if (s0 + j < NSAMP) {
                        mx = fmaxf(mx, acc[i][j]);
                        smv += acc[i][j];
                    }
                }
                pmx[st * 84 + q] = mx;
                psm[st * 84 + q] = smv;
            }
        }
    }
    __syncthreads();

    // reduce partials -> M[q] = max_s - sum_s / 81
    if (tid < LL) {
        float mx = -FLT_MAX, smv = 0.0f;
        #pragma unroll
        for (int st = 0; st < 11; st++) {
            mx = fmaxf(mx, pmx[st * 84 + tid]);
            smv += psm[st * 84 + tid];
        }
        Ms[tid] = mx - smv * (1.0f / 81.0f);
    }
    __syncthreads();

    // ---- Phase C: warp-parallel top-10 (tie -> lower index, matching top_k) ----
    if (warp == 0) {
        float m0 = (lane      < LL) ? Ms[lane]      : -FLT_MAX;
        float m1 = (lane + 32 < LL) ? Ms[lane + 32] : -FLT_MAX;
        float m2 = (lane + 64 < LL) ? Ms[lane + 64] : -FLT_MAX;
        #pragma unroll
        for (int r = 0; r < UU; r++) {
            float bv = m0; int bi = lane;
            if (m1 > bv) { bv = m1; bi = lane + 32; }
            if (m2 > bv) { bv = m2; bi = lane + 64; }
            #pragma unroll
            for (int o = 16; o > 0; o >>= 1) {
                float ov = __shfl_xor_sync(0xffffffffu, bv, o);
                int   oi = __shfl_xor_sync(0xffffffffu, bi, o);
                if (ov > bv || (ov == bv && oi < bi)) { bv = ov; bi = oi; }
            }
            if (lane == 0) { topi[r] = bi; rank_of[bi] = r; }
            if (bi == lane)           m0 = -FLT_MAX;
            else if (bi == lane + 32) m1 = -FLT_MAX;
            else if (bi == lane + 64) m2 = -FLT_MAX;
        }
    }
    __syncthreads();

    // ---- Phase D: full scores for selected rows, softmax, attn out, PV ----
    const float scale = 0.125f; // 1/sqrt(64)
    for (int r = warp; r < UU; r += 8) {
        const int qi = topi[r];
        const float* qr = Qs + qi * QSTR;
        const int ri = r / WS, rj = r % WS;   // bias row indexed by RANK (ref quirk)

        float sc[3];
        float mx = -FLT_MAX;
        #pragma unroll
        for (int t = 0; t < 3; t++) {
            int k = lane + t * 32;
            float v = -FLT_MAX;
            if (k < LL) {
                const float* kr = Ks + k * KSTR;
                float a = 0.0f;
                #pragma unroll 4
                for (int d = 0; d < DD; d += 4) {
                    float4 qv = *(const float4*)(qr + d);
                    float4 kv = *(const float4*)(kr + d);
                    a += qv.x*kv.x + qv.y*kv.y + qv.z*kv.z + qv.w*kv.w;
                }
                int ki = k / WS, kj = k - ki * WS;
                int bidx = (ri - ki + (WS - 1)) * (2 * WS - 1) + (rj - kj + (WS - 1));
                v = (a + biass[bidx]) * scale;
            }
            sc[t] = v;
            mx = fmaxf(mx, v);
        }
        #pragma unroll
        for (int o = 16; o > 0; o >>= 1)
            mx = fmaxf(mx, __shfl_xor_sync(0xffffffffu, mx, o));

        float sum = 0.0f;
        #pragma unroll
        for (int t = 0; t < 3; t++) {
            int k = lane + t * 32;
            if (k < LL) { sc[t] = __expf(sc[t] - mx); sum += sc[t]; }
            else sc[t] = 0.0f;
        }
        #pragma unroll
        for (int o = 16; o > 0; o >>= 1)
            sum += __shfl_xor_sync(0xffffffffu, sum, o);
        const float inv = 1.0f / sum;

        // normalize, write attn out directly
        float* ao = out_attn ? out_attn + (((size_t)b * HH + h) * UU + r) * LL : (float*)0;
        #pragma unroll
        for (int t = 0; t < 3; t++) {
            int k = lane + t * 32;
            sc[t] *= inv;
            if (ao && k < LL) ao[k] = sc[t];
        }

        // PV: broadcast attn weights via shfl, accumulate per-lane d columns
        float a0 = 0.0f, a1 = 0.0f;
        for (int k = 0; k < LL; k++) {
            float a = __shfl_sync(0xffffffffu, sc[k >> 5], k & 31);
            a0 += a * Vs[k * DD + lane];
            a1 += a * Vs[k * DD + lane + 32];
        }
        upds[r * DD + lane]      = a0;
        upds[r * DD + lane + 32] = a1;
    }
    __syncthreads();

    // ---- Phase E: cumsum(V) with selected rows replaced; write into Qs ----
    if (tid < DD) {
        const int d = tid;
        float acc = 0.0f;
        for (int l = 0; l < LL; l++) {
            acc += Vs[l * DD + d];
            int r = rank_of[l];
            Qs[l * QSTR + d] = (r >= 0) ? upds[r * DD + d] : acc;
        }
    }
    __syncthreads();

    // ---- write context (coalesced float4) ----
    float* ob = out_ctx + base;
    for (int idx = tid; idx < LL * 16; idx += NTHREADS) {
        int row = idx >> 4;
        int vec = idx & 15;
        *(float4*)(ob + (size_t)row * (HH * DD) + vec * 4) =
            *(const float4*)(Qs + row * QSTR + vec * 4);
    }
}

extern "C" void kernel_launch(void* const* d_in, const int* in_sizes, int n_in,
                              void* d_out, int out_size)
{
    const float* q    = (const float*)d_in[0];
    const float* k    = (const float*)d_in[1];
    const float* v    = (const float*)d_in[2];
    const float* bias = (const float*)d_in[3];
    float* out = (float*)d_out;

    const long long ctx_elems  = (long long)BB * LL * HH * DD;   // 42,467,328
    const long long attn_elems = (long long)BB * HH * UU * LL;   //  6,635,520
    float* attn_out = ((long long)out_size >= ctx_elems + attn_elems)
                        ? out + ctx_elems : (float*)0;

    cudaFuncSetAttribute(prob_attn_kernel,
                         cudaFuncAttributeMaxDynamicSharedMemorySize, SM_BYTES);
    prob_attn_kernel<<<BB * HH, NTHREADS, SM_BYTES>>>(q, k, v, bias, out, attn_out);
}

// round 3
// speedup vs baseline: 3.4209x; 1.4724x over previous
#include <cuda_runtime.h>
#include <math.h>
#include <float.h>

// Problem constants (fixed by the dataset)
#define BB 1024
#define LL 81      // sequence length = WS*WS
#define HH 8
#define DD 64
#define UU 10      // top-k rows
#define NSAMP 41   // (81+1)/2 even-index key samples
#define WS 9
#define QSTR 68    // padded Q row stride (floats)
#define KSTR 68    // padded K row stride (floats)

#define NTHREADS 256

// Shared memory layout (floats):
//   Qs   : 81*68 = 5508
//   Ks   : 81*68 = 5508
//   Vs   : 81*64 = 5184
//   bias : 289
//   Ms   : 84
//   pmx  : 11*84 = 924   (phase-B partial max; reused as csum in phase E)
//   psm  : 11*84 = 924
//   upd  : 10*64 = 640
//   topi : 16 ints, rank_of : 81 ints
#define SM_FLOATS (81*QSTR + 81*KSTR + 81*DD + 289 + 84 + 924 + 924 + 640)
#define SM_BYTES  (SM_FLOATS*4 + (16 + 81)*4)

__global__ __launch_bounds__(NTHREADS, 3)
void prob_attn_kernel(const float* __restrict__ q_in,
                      const float* __restrict__ k_in,
                      const float* __restrict__ v_in,
                      const float* __restrict__ bias_in,
                      float* __restrict__ out_ctx,
                      float* __restrict__ out_attn)
{
    extern __shared__ float sm[];
    float* Qs    = sm;
    float* Ks    = Qs + 81*QSTR;
    float* Vs    = Ks + 81*KSTR;
    float* biass = Vs + 81*DD;
    float* Ms    = biass + 289;
    float* pmx   = Ms + 84;
    float* psm   = pmx + 924;
    float* upds  = psm + 924;
    int*   topi  = (int*)(upds + 640);
    int*   rank_of = topi + 16;

    const int tid  = threadIdx.x;
    const int warp = tid >> 5;
    const int lane = tid & 31;

    const int blk = blockIdx.x;
    const int b = blk >> 3;
    const int h = blk & 7;

    const size_t base = ((size_t)b * LL * HH + h) * DD;   // row l at base + l*HH*DD
    const float* qb = q_in + base;
    const float* kb = k_in + base;
    const float* vb = v_in + base;

    // ---- Phase A: load tiles (coalesced float4), bias, init rank map ----
    for (int idx = tid; idx < LL * 16; idx += NTHREADS) {
        int row = idx >> 4;
        int vec = idx & 15;
        size_t goff = (size_t)row * (HH * DD) + vec * 4;
        float4 qv = *(const float4*)(qb + goff);
        float4 kv = *(const float4*)(kb + goff);
        float4 vv = *(const float4*)(vb + goff);
        *(float4*)(Qs + row*QSTR + vec*4) = qv;
        *(float4*)(Ks + row*KSTR + vec*4) = kv;
        *(float4*)(Vs + row*DD   + vec*4) = vv;
    }
    for (int i = tid; i < 289; i += NTHREADS) biass[i] = bias_in[i];
    if (tid < LL) rank_of[tid] = -1;
    __syncthreads();

    // ---- Phase B: sampled scores, register-tiled 4q x 4s per thread.
    //      q rows interleaved with stride 21 -> consecutive lanes differ by ONE
    //      row (68 words == bank-group stride 1) -> conflict-free LDS.128.
    //      s tiles interleaved with stride 11 (K loads broadcast within st-group).
    if (tid < 231) {
        const int st = tid / 21;        // 0..10
        const int qt = tid - st * 21;   // 0..20

        const float* Qr[4];
        const float* Kr[4];
        #pragma unroll
        for (int i = 0; i < 4; i++) {
            int q = qt + 21 * i; if (q > 80) q = 80;   // clamp (masked later)
            Qr[i] = Qs + q * QSTR;
        }
        #pragma unroll
        for (int j = 0; j < 4; j++) {
            int s = st + 11 * j; if (s > 40) s = 40;   // clamp (masked later)
            Kr[j] = Ks + (2 * s) * KSTR;
        }

        float acc[4][4];
        #pragma unroll
        for (int i = 0; i < 4; i++)
            #pragma unroll
            for (int j = 0; j < 4; j++) acc[i][j] = 0.0f;

        #pragma unroll 2
        for (int d = 0; d < DD; d += 4) {
            float4 qv[4], kv[4];
            #pragma unroll
            for (int i = 0; i < 4; i++) qv[i] = *(const float4*)(Qr[i] + d);
            #pragma unroll
            for (int j = 0; j < 4; j++) kv[j] = *(const float4*)(Kr[j] + d);
            #pragma unroll
            for (int i = 0; i < 4; i++)
                #pragma unroll
                for (int j = 0; j < 4; j++)
                    acc[i][j] += qv[i].x*kv[j].x + qv[i].y*kv[j].y
                               + qv[i].z*kv[j].z + qv[i].w*kv[j].w;
        }

        #pragma unroll
        for (int i = 0; i < 4; i++) {
            int q = qt + 21 * i;
            if (q < LL) {
                float mx = -FLT_MAX, smv = 0.0f;
                #pragma unroll
                for (int j = 0; j < 4; j++) {
                    if (st + 11 * j < NSAMP) {
                        mx = fmaxf(mx, acc[i][j]);
                        smv += acc[i][j];
                    }
                }
                pmx[st * 84 + q] = mx;
                psm[st * 84 + q] = smv;
            }
        }
    }
    __syncthreads();

    // reduce partials -> M[q] = max_s - sum_s / 81
    if (tid < LL) {
        float mx = -FLT_MAX, smv = 0.0f;
        #pragma unroll
        for (int st = 0; st < 11; st++) {
            mx = fmaxf(mx, pmx[st * 84 + tid]);
            smv += psm[st * 84 + tid];
        }
        Ms[tid] = mx - smv * (1.0f / 81.0f);
    }
    __syncthreads();

    // ---- Phase C: warp-parallel top-10 (tie -> lower index, matching top_k) ----
    if (warp == 0) {
        float m0 = (lane      < LL) ? Ms[lane]      : -FLT_MAX;
        float m1 = (lane + 32 < LL) ? Ms[lane + 32] : -FLT_MAX;
        float m2 = (lane + 64 < LL) ? Ms[lane + 64] : -FLT_MAX;
        #pragma unroll
        for (int r = 0; r < UU; r++) {
            float bv = m0; int bi = lane;
            if (m1 > bv) { bv = m1; bi = lane + 32; }
            if (m2 > bv) { bv = m2; bi = lane + 64; }
            #pragma unroll
            for (int o = 16; o > 0; o >>= 1) {
                float ov = __shfl_xor_sync(0xffffffffu, bv, o);
                int   oi = __shfl_xor_sync(0xffffffffu, bi, o);
                if (ov > bv || (ov == bv && oi < bi)) { bv = ov; bi = oi; }
            }
            if (lane == 0) { topi[r] = bi; rank_of[bi] = r; }
            if (bi == lane)           m0 = -FLT_MAX;
            else if (bi == lane + 32) m1 = -FLT_MAX;
            else if (bi == lane + 64) m2 = -FLT_MAX;
        }
    }
    __syncthreads();

    // ---- Phase D: full scores for selected rows, softmax, attn out, PV ----
    const float scale = 0.125f; // 1/sqrt(64)
    for (int r = warp; r < UU; r += 8) {
        const int qi = topi[r];
        const float* qr = Qs + qi * QSTR;
        const int ri = r / WS, rj = r % WS;   // bias row indexed by RANK (ref quirk)

        float sc[3];
        float mx = -FLT_MAX;
        #pragma unroll
        for (int t = 0; t < 3; t++) {
            int k = lane + t * 32;
            float v = -FLT_MAX;
            if (k < LL) {
                const float* kr = Ks + k * KSTR;   // lane stride 68 words: conflict-free
                float a = 0.0f;
                #pragma unroll 4
                for (int d = 0; d < DD; d += 4) {
                    float4 qv = *(const float4*)(qr + d);   // broadcast
                    float4 kv = *(const float4*)(kr + d);
                    a += qv.x*kv.x + qv.y*kv.y + qv.z*kv.z + qv.w*kv.w;
                }
                int ki = k / WS, kj = k - ki * WS;
                int bidx = (ri - ki + (WS - 1)) * (2 * WS - 1) + (rj - kj + (WS - 1));
                v = (a + biass[bidx]) * scale;
            }
            sc[t] = v;
            mx = fmaxf(mx, v);
        }
        #pragma unroll
        for (int o = 16; o > 0; o >>= 1)
            mx = fmaxf(mx, __shfl_xor_sync(0xffffffffu, mx, o));

        float sum = 0.0f;
        #pragma unroll
        for (int t = 0; t < 3; t++) {
            int k = lane + t * 32;
            if (k < LL) { sc[t] = __expf(sc[t] - mx); sum += sc[t]; }
            else sc[t] = 0.0f;
        }
        #pragma unroll
        for (int o = 16; o > 0; o >>= 1)
            sum += __shfl_xor_sync(0xffffffffu, sum, o);
        const float inv = 1.0f / sum;

        // normalize, write attn out directly
        float* ao = out_attn ? out_attn + (((size_t)b * HH + h) * UU + r) * LL : (float*)0;
        #pragma unroll
        for (int t = 0; t < 3; t++) {
            int k = lane + t * 32;
            sc[t] *= inv;
            if (ao && k < LL) ao[k] = sc[t];
        }

        // PV: broadcast attn weights via shfl, accumulate per-lane d columns
        float a0 = 0.0f, a1 = 0.0f;
        for (int k = 0; k < LL; k++) {
            float a = __shfl_sync(0xffffffffu, sc[k >> 5], k & 31);
            a0 += a * Vs[k * DD + lane];
            a1 += a * Vs[k * DD + lane + 32];
        }
        upds[r * DD + lane]      = a0;
        upds[r * DD + lane + 32] = a1;
    }
    __syncthreads();

    // ---- Phase E: blocked cumsum(V) scan (3 chunks of 27) with selected rows
    //      replaced by upd, fused directly into the gmem context write. ----
    float* csum = pmx;   // reuse (>=128 floats free)
    if (tid < 128) {
        const int d = tid & 63;
        const int c = tid >> 6;           // 0,1
        float s = 0.0f;
        const int l0 = c * 27;
        #pragma unroll 9
        for (int l = l0; l < l0 + 27; l++) s += Vs[l * DD + d];
        csum[c * 64 + d] = s;
    }
    __syncthreads();
    if (tid < 192) {
        const int d = tid & 63;
        const int c = tid >> 6;           // 0,1,2
        float acc = 0.0f;
        if (c > 0) acc += csum[d];
        if (c > 1) acc += csum[64 + d];
        float* ob = out_ctx + base + d;
        const int l0 = c * 27;
        for (int l = l0; l < l0 + 27; l++) {
            acc += Vs[l * DD + d];
            int r = rank_of[l];
            ob[(size_t)l * (HH * DD)] = (r >= 0) ? upds[r * DD + d] : acc;
        }
    }
}

extern "C" void kernel_launch(void* const* d_in, const int* in_sizes, int n_in,
                              void* d_out, int out_size)
{
    const float* q    = (const float*)d_in[0];
    const float* k    = (const float*)d_in[1];
    const float* v    = (const float*)d_in[2];
    const float* bias = (const float*)d_in[3];
    float* out = (float*)d_out;

    const long long ctx_elems  = (long long)BB * LL * HH * DD;   // 42,467,328
    const long long attn_elems = (long long)BB * HH * UU * LL;   //  6,635,520
    float* attn_out = ((long long)out_size >= ctx_elems + attn_elems)
                        ? out + ctx_elems : (float*)0;

    cudaFuncSetAttribute(prob_attn_kernel,
                         cudaFuncAttributeMaxDynamicSharedMemorySize, SM_BYTES);
    prob_attn_kernel<<<BB * HH, NTHREADS, SM_BYTES>>>(q, k, v, bias, out, attn_out);
}